// round 16
// baseline (speedup 1.0000x reference)
#include <cuda_runtime.h>
#include <cuda_fp16.h>
#include <cstdint>

#define N_NODES  50000
#define N_EDGES  640000
#define D        128
#define N_GRAPHS 64
#define CAP      64                  // per-node edge bucket capacity

#define GEMM_BLOCKS   391            // ceil(50000/128)
#define FILL_BLOCKS   2500           // 640000/256 (1 edge per thread)
#define PACK_BLOCKS   3125           // 50000*16 / 256
#define CLEAN_BLOCKS  200            // 64 out-gemm + 136 cleanup
#define GATHER_BLOCKS 12500          // 50000 nodes / 4 per block (2 warps/node)

// ---------------- scratch (device globals; zero-initialized at load) --------
// INVARIANT: g_fill and g_y are zero on entry to kernel_launch and re-zeroed
// by the tail kernel, so every graph replay sees clean state.
__device__ __half g_h16[N_NODES * D];           // gemm1 output (fp16)
__device__ __half g_z16[N_NODES * D];           // layer-1 activation (fp16)
__device__ int    g_fill[N_NODES];              // bucket cursors == degrees
// bucket CSR. fill writes raw src ids into slots [0, deg); pack_kernel then
// rewrites those slots in place as: low 16 = src id (N_NODES < 65536),
// high 16 = fp16 norm. Slots >= deg are never read; raw ids < 65536 so
// "& 0xFFFF" is identity on freshly-filled slots.
__device__ __align__(16) unsigned g_sbuf[N_NODES * CAP];
__device__ float  g_y[N_GRAPHS * D];            // pooled sums (atomic accum)

// ---------------- helpers ----------------------------------------------------
__device__ __forceinline__ unsigned h2u(__half2 h) {
    union { __half2 h; unsigned u; } c; c.h = h; return c.u;
}
__device__ __forceinline__ __half2 u2h(unsigned u) {
    union { unsigned u; __half2 h; } c; c.u = u; return c.h;
}

// ---------------- GEMM1: h16[M,128] = fp16( X @ W1 ), tensor cores ----------
__global__ void __launch_bounds__(256) gemm_mma_kernel(
        const float* __restrict__ X, const float* __restrict__ W,
        __half* __restrict__ OUT16) {
    __shared__ __half As[128][72];
    __shared__ __half Bs[128][72];

    const int tid  = threadIdx.x;
    const int warp = tid >> 5;
    const int lane = tid & 31;
    const int g    = lane >> 2;
    const int t    = lane & 3;
    const int row0 = blockIdx.x * 128;
    const int wrow = warp * 16;

    float c[16][4];
#pragma unroll
    for (int j = 0; j < 16; ++j)
#pragma unroll
        for (int q = 0; q < 4; ++q) c[j][q] = 0.f;

    for (int stage = 0; stage < 2; ++stage) {
        const int k0 = stage * 64;
#pragma unroll
        for (int it = 0; it < 8; ++it) {
            int f4  = it * 256 + tid;
            int row = f4 >> 4;
            int c4  = f4 & 15;
            float4 v = make_float4(0.f, 0.f, 0.f, 0.f);
            if (row0 + row < N_NODES)
                v = *(const float4*)&X[(size_t)(row0 + row) * D + k0 + c4 * 4];
            __half2 h0 = __floats2half2_rn(v.x, v.y);
            __half2 h1 = __floats2half2_rn(v.z, v.w);
            uint2 pk; pk.x = h2u(h0); pk.y = h2u(h1);
            *(uint2*)&As[row][c4 * 4] = pk;
        }
#pragma unroll
        for (int it = 0; it < 16; ++it) {
            int p  = it * 256 + tid;
            int n  = p & 127;
            int kp = p >> 7;
            float w0 = W[(size_t)(k0 + 2 * kp) * D + n];
            float w1 = W[(size_t)(k0 + 2 * kp + 1) * D + n];
            __half2 h = __floats2half2_rn(w0, w1);
            *(unsigned*)&Bs[n][2 * kp] = h2u(h);
        }
        __syncthreads();

#pragma unroll
        for (int ks = 0; ks < 4; ++ks) {
            unsigned ra0 = *(const unsigned*)&As[wrow + g][ks * 16 + t * 2];
            unsigned ra1 = *(const unsigned*)&As[wrow + g + 8][ks * 16 + t * 2];
            unsigned ra2 = *(const unsigned*)&As[wrow + g][ks * 16 + t * 2 + 8];
            unsigned ra3 = *(const unsigned*)&As[wrow + g + 8][ks * 16 + t * 2 + 8];
#pragma unroll
            for (int j = 0; j < 16; ++j) {
                unsigned rb0 = *(const unsigned*)&Bs[j * 8 + g][ks * 16 + t * 2];
                unsigned rb1 = *(const unsigned*)&Bs[j * 8 + g][ks * 16 + t * 2 + 8];
                asm volatile(
                    "mma.sync.aligned.m16n8k16.row.col.f32.f16.f16.f32 "
                    "{%0,%1,%2,%3}, {%4,%5,%6,%7}, {%8,%9}, {%0,%1,%2,%3};"
                    : "+f"(c[j][0]), "+f"(c[j][1]), "+f"(c[j][2]), "+f"(c[j][3])
                    : "r"(ra0), "r"(ra1), "r"(ra2), "r"(ra3), "r"(rb0), "r"(rb1));
            }
        }
        __syncthreads();
    }

    int row_a = row0 + wrow + g;
    int row_b = row_a + 8;
#pragma unroll
    for (int j = 0; j < 16; ++j) {
        if (row_a < N_NODES) {
            __half2 p = __floats2half2_rn(c[j][0], c[j][1]);
            *(unsigned*)&OUT16[(size_t)row_a * D + j * 8 + t * 2] = h2u(p);
        }
        if (row_b < N_NODES) {
            __half2 p = __floats2half2_rn(c[j][2], c[j][3]);
            *(unsigned*)&OUT16[(size_t)row_b * D + j * 8 + t * 2] = h2u(p);
        }
    }
}

// ---------------- bucket CSR fill (1 edge per thread; r11-proven) ------------
__global__ void fill_kernel(const int* __restrict__ ei) {
    int i = blockIdx.x * 256 + threadIdx.x;        // exact 640000
    int src = ei[i];
    int dst = ei[N_EDGES + i];
    int pos = atomicAdd(&g_fill[dst], 1);
    if (pos < CAP) g_sbuf[dst * CAP + pos] = (unsigned)src;
}

// Pack in place: slot -> src | (fp16(rsqrt((deg_s+1)*(deg_d+1))) << 16).
// Thread-per-4-slots; rsqrt(a)*rsqrt(b) == rsqrt(a*b) within ~1e-7.
__global__ void __launch_bounds__(256) pack_kernel() {
    int t = blockIdx.x * 256 + threadIdx.x;        // exact 800000
    int node = t >> 4;
    int base = (t & 15) * 4;
    int deg = g_fill[node];
    int degc = deg < CAP ? deg : CAP;
    if (base >= degc) return;
    float fd = (float)(deg + 1);
    uint4 v = *(const uint4*)&g_sbuf[node * CAP + base];
    int n = degc - base;
    {
        unsigned s = v.x & 0xFFFFu;
        float nm = rsqrtf(fd * (float)(g_fill[s] + 1));
        v.x = s | ((unsigned)__half_as_ushort(__float2half(nm)) << 16);
    }
    if (n > 1) {
        unsigned s = v.y & 0xFFFFu;
        float nm = rsqrtf(fd * (float)(g_fill[s] + 1));
        v.y = s | ((unsigned)__half_as_ushort(__float2half(nm)) << 16);
    }
    if (n > 2) {
        unsigned s = v.z & 0xFFFFu;
        float nm = rsqrtf(fd * (float)(g_fill[s] + 1));
        v.z = s | ((unsigned)__half_as_ushort(__float2half(nm)) << 16);
    }
    if (n > 3) {
        unsigned s = v.w & 0xFFFFu;
        float nm = rsqrtf(fd * (float)(g_fill[s] + 1));
        v.w = s | ((unsigned)__half_as_ushort(__float2half(nm)) << 16);
    }
    *(uint4*)&g_sbuf[node * CAP + base] = v;
}

// ---------------- feature-split gather core ----------------------------------
// 2 warps per node: warp half h owns features [h*64, h*64+64). Each lane owns
// 2 features (one half2 word, index off = h*32+lane into the 64-word row).
// Dual accumulators (even/odd edges) halve the HFMA2 dependency chain.
__device__ __forceinline__ void acc_fs(const __half* __restrict__ H,
                                       unsigned pk, int off, __half2& a) {
    unsigned s = pk & 0xFFFFu;
    __half2 nm2 = u2h(__byte_perm(pk, pk, 0x3232));   // (nm, nm)
    unsigned u = ((const unsigned*)(H + (size_t)s * D))[off];
    a = __hfma2(u2h(u), nm2, a);
}

__device__ __forceinline__ __half2 gather_node_fs(
        const __half* __restrict__ H, int node, int off) {
    int deg = g_fill[node];
    int degc = deg < CAP ? deg : CAP;
    float nms = __fdividef(1.f, (float)(deg + 1));    // dinv^2
    __half2 a0 = __float2half2_rn(0.f), a1 = __float2half2_rn(0.f);
    // self-loop
    {
        unsigned u = ((const unsigned*)(H + (size_t)node * D))[off];
        a0 = __hfma2(u2h(u), __float2half2_rn(nms), a0);
    }
    const uint4* sb = (const uint4*)(g_sbuf + node * CAP);
    int e = 0;
    for (; e + 8 <= degc; e += 8) {
        uint4 sa = sb[e >> 2];
        uint4 sc = sb[(e >> 2) + 1];
        acc_fs(H, sa.x, off, a0);
        acc_fs(H, sa.y, off, a1);
        acc_fs(H, sa.z, off, a0);
        acc_fs(H, sa.w, off, a1);
        acc_fs(H, sc.x, off, a0);
        acc_fs(H, sc.y, off, a1);
        acc_fs(H, sc.z, off, a0);
        acc_fs(H, sc.w, off, a1);
    }
    if (e + 4 <= degc) {
        uint4 sa = sb[e >> 2];
        acc_fs(H, sa.x, off, a0);
        acc_fs(H, sa.y, off, a1);
        acc_fs(H, sa.z, off, a0);
        acc_fs(H, sa.w, off, a1);
        e += 4;
    }
    for (; e < degc; ++e)
        acc_fs(H, g_sbuf[node * CAP + e], off, a0);
    return __hadd2(a0, a1);
}

// layer-1: z16 = fp16( relu( Ahat*h + b1 ) ); 2 warps/node, no cross-warp comm
__global__ void __launch_bounds__(256) gather1_kernel(
        const float* __restrict__ bias) {
    const int warp = threadIdx.x >> 5;
    const int lane = threadIdx.x & 31;
    const int node = blockIdx.x * 4 + (warp >> 1);   // exact 50000
    const int half = warp & 1;
    const int off  = half * 32 + lane;               // half2-word index in row

    __half2 a = gather_node_fs(g_h16, node, off);

    float2 f = __half22float2(a);
    float2 b = *(const float2*)&bias[off * 2];
    float rx = fmaxf(f.x + b.x, 0.f);
    float ry = fmaxf(f.y + b.y, 0.f);
    ((unsigned*)(g_z16 + (size_t)node * D))[off] = h2u(__floats2half2_rn(rx, ry));
}

// layer-2 + fused pool: g_y[batch[node]] += Ahat*z  (block = 4 nodes)
__global__ void __launch_bounds__(256) gather2_kernel(
        const int* __restrict__ batch) {
    __shared__ float part[4][128];
    __shared__ int   sgr[4];

    const int warp = threadIdx.x >> 5;
    const int lane = threadIdx.x & 31;
    const int node = blockIdx.x * 4 + (warp >> 1);   // exact 50000
    const int half = warp & 1;
    const int off  = half * 32 + lane;

    __half2 a = gather_node_fs(g_z16, node, off);

    float2 f = __half22float2(a);
    *(float2*)&part[warp >> 1][off * 2] = f;
    if (lane == 0 && half == 0) sgr[warp >> 1] = batch[node];
    __syncthreads();

    if (threadIdx.x < 128) {
        int d = threadIdx.x;
        float acc = part[0][d];
        int gc = sgr[0];
#pragma unroll
        for (int w = 1; w < 4; ++w) {
            int gw = sgr[w];
            if (gw != gc) {
                atomicAdd(&g_y[gc * D + d], acc);
                acc = 0.f; gc = gw;
            }
            acc += part[w][d];
        }
        atomicAdd(&g_y[gc * D + d], acc);
    }
}

// out[g] = (g_y[g]/cnt_g) @ W2 + b2 ; cnt via binary search on sorted batch;
// then restore zeroed-scratch invariant.
__global__ void out_clean_kernel(const int* __restrict__ batch,
                                 const float* __restrict__ W2,
                                 const float* __restrict__ b2,
                                 float* __restrict__ out) {
    int b = blockIdx.x;
    if (b < N_GRAPHS) {
        __shared__ float ys[D];
        int g = b, d = threadIdx.x;
        int lo = 0, hi = N_NODES;
        while (lo < hi) { int m = (lo + hi) >> 1; if (batch[m] < g) lo = m + 1; else hi = m; }
        int start = lo;
        lo = 0; hi = N_NODES;
        while (lo < hi) { int m = (lo + hi) >> 1; if (batch[m] < g + 1) lo = m + 1; else hi = m; }
        float cnt = fmaxf((float)(lo - start), 1.f);

        ys[d] = g_y[g * D + d] / cnt;
        g_y[g * D + d] = 0.f;            // restore invariant
        __syncthreads();
        float acc = b2[d];
#pragma unroll 8
        for (int k = 0; k < D; ++k) acc += ys[k] * W2[k * D + d];
        out[g * D + d] = acc;
    } else {
        const int nthr = (CLEAN_BLOCKS - N_GRAPHS) * 128;
        int i = (b - N_GRAPHS) * 128 + threadIdx.x;
        for (int j = i; j < N_NODES; j += nthr) g_fill[j] = 0;
    }
}

// ---------------- launch -----------------------------------------------------

extern "C" void kernel_launch(void* const* d_in, const int* in_sizes, int n_in,
                              void* d_out, int out_size) {
    const float* x     = (const float*)d_in[0];
    const int*   ei    = (const int*)d_in[1];    // int32 (JAX x64 disabled)
    const int*   batch = (const int*)d_in[2];
    const float* W1    = (const float*)d_in[3];
    const float* b1    = (const float*)d_in[4];
    const float* W2    = (const float*)d_in[5];
    const float* b2    = (const float*)d_in[6];
    float*       out   = (float*)d_out;

    __half* h16; cudaGetSymbolAddress((void**)&h16, g_h16);

    static cudaStream_t s_side = nullptr;
    static cudaEvent_t  e_fork = nullptr, e_join = nullptr;
    if (s_side == nullptr) {
        cudaStreamCreateWithFlags(&s_side, cudaStreamNonBlocking);
        cudaEventCreateWithFlags(&e_fork, cudaEventDisableTiming);
        cudaEventCreateWithFlags(&e_join, cudaEventDisableTiming);
    }

    // fork: main = GEMM1 (tensor/smem) ; side = fill -> pack (LSU)
    cudaEventRecord(e_fork, 0);
    cudaStreamWaitEvent(s_side, e_fork, 0);

    gemm_mma_kernel<<<GEMM_BLOCKS, 256>>>(x, W1, h16);

    fill_kernel<<<FILL_BLOCKS, 256, 0, s_side>>>(ei);
    pack_kernel<<<PACK_BLOCKS, 256, 0, s_side>>>();
    cudaEventRecord(e_join, s_side);
    cudaStreamWaitEvent(0, e_join, 0);

    // join: gather1 -> gather2 -> out/clean
    gather1_kernel<<<GATHER_BLOCKS, 256>>>(b1);
    gather2_kernel<<<GATHER_BLOCKS, 256>>>(batch);
    out_clean_kernel<<<CLEAN_BLOCKS, D>>>(batch, W2, b2, out);
}

// round 17
// speedup vs baseline: 1.2597x; 1.2597x over previous
#include <cuda_runtime.h>
#include <cuda_fp16.h>
#include <cstdint>

#define N_NODES  50000
#define N_EDGES  640000
#define D        128
#define N_GRAPHS 64
#define CAP      64                  // per-node edge bucket capacity

#define GEMM_BLOCKS   391            // ceil(50000/128)
#define FILL_BLOCKS   2500           // 640000/256 (1 edge per thread)
#define PACK_BLOCKS   3125           // 50000*16 / 256
#define CLEAN_BLOCKS  200            // 64 out-gemm + 136 cleanup
#define GATHER_BLOCKS 6250           // 50000 / 8 warps (1 warp per node)

// ---------------- scratch (device globals; zero-initialized at load) --------
// INVARIANT: g_fill and g_y are zero on entry to kernel_launch and re-zeroed
// by the tail kernel, so every graph replay sees clean state.
__device__ __half g_h16[N_NODES * D];           // gemm1 output (fp16)
__device__ __half g_z16[N_NODES * D];           // layer-1 activation (fp16)
__device__ int    g_fill[N_NODES];              // bucket cursors == degrees
// bucket CSR. fill writes raw src ids into slots [0, deg); pack_kernel then
// rewrites those slots in place as: low 16 = src id (N_NODES < 65536),
// high 16 = fp16 norm. Slots >= deg are never read; raw ids < 65536 so
// "& 0xFFFF" is identity on freshly-filled slots.
__device__ __align__(16) unsigned g_sbuf[N_NODES * CAP];
__device__ float  g_y[N_GRAPHS * D];            // pooled sums (atomic accum)

// ---------------- helpers ----------------------------------------------------
__device__ __forceinline__ unsigned h2u(__half2 h) {
    union { __half2 h; unsigned u; } c; c.h = h; return c.u;
}
__device__ __forceinline__ __half2 u2h(unsigned u) {
    union { unsigned u; __half2 h; } c; c.u = u; return c.h;
}

// ---------------- GEMM1: h16[M,128] = fp16( X @ W1 ), tensor cores ----------
__global__ void __launch_bounds__(256) gemm_mma_kernel(
        const float* __restrict__ X, const float* __restrict__ W,
        __half* __restrict__ OUT16) {
    __shared__ __half As[128][72];
    __shared__ __half Bs[128][72];

    const int tid  = threadIdx.x;
    const int warp = tid >> 5;
    const int lane = tid & 31;
    const int g    = lane >> 2;
    const int t    = lane & 3;
    const int row0 = blockIdx.x * 128;
    const int wrow = warp * 16;

    float c[16][4];
#pragma unroll
    for (int j = 0; j < 16; ++j)
#pragma unroll
        for (int q = 0; q < 4; ++q) c[j][q] = 0.f;

    for (int stage = 0; stage < 2; ++stage) {
        const int k0 = stage * 64;
#pragma unroll
        for (int it = 0; it < 8; ++it) {
            int f4  = it * 256 + tid;
            int row = f4 >> 4;
            int c4  = f4 & 15;
            float4 v = make_float4(0.f, 0.f, 0.f, 0.f);
            if (row0 + row < N_NODES)
                v = *(const float4*)&X[(size_t)(row0 + row) * D + k0 + c4 * 4];
            __half2 h0 = __floats2half2_rn(v.x, v.y);
            __half2 h1 = __floats2half2_rn(v.z, v.w);
            uint2 pk; pk.x = h2u(h0); pk.y = h2u(h1);
            *(uint2*)&As[row][c4 * 4] = pk;
        }
#pragma unroll
        for (int it = 0; it < 16; ++it) {
            int p  = it * 256 + tid;
            int n  = p & 127;
            int kp = p >> 7;
            float w0 = W[(size_t)(k0 + 2 * kp) * D + n];
            float w1 = W[(size_t)(k0 + 2 * kp + 1) * D + n];
            __half2 h = __floats2half2_rn(w0, w1);
            *(unsigned*)&Bs[n][2 * kp] = h2u(h);
        }
        __syncthreads();

#pragma unroll
        for (int ks = 0; ks < 4; ++ks) {
            unsigned ra0 = *(const unsigned*)&As[wrow + g][ks * 16 + t * 2];
            unsigned ra1 = *(const unsigned*)&As[wrow + g + 8][ks * 16 + t * 2];
            unsigned ra2 = *(const unsigned*)&As[wrow + g][ks * 16 + t * 2 + 8];
            unsigned ra3 = *(const unsigned*)&As[wrow + g + 8][ks * 16 + t * 2 + 8];
#pragma unroll
            for (int j = 0; j < 16; ++j) {
                unsigned rb0 = *(const unsigned*)&Bs[j * 8 + g][ks * 16 + t * 2];
                unsigned rb1 = *(const unsigned*)&Bs[j * 8 + g][ks * 16 + t * 2 + 8];
                asm volatile(
                    "mma.sync.aligned.m16n8k16.row.col.f32.f16.f16.f32 "
                    "{%0,%1,%2,%3}, {%4,%5,%6,%7}, {%8,%9}, {%0,%1,%2,%3};"
                    : "+f"(c[j][0]), "+f"(c[j][1]), "+f"(c[j][2]), "+f"(c[j][3])
                    : "r"(ra0), "r"(ra1), "r"(ra2), "r"(ra3), "r"(rb0), "r"(rb1));
            }
        }
        __syncthreads();
    }

    int row_a = row0 + wrow + g;
    int row_b = row_a + 8;
#pragma unroll
    for (int j = 0; j < 16; ++j) {
        if (row_a < N_NODES) {
            __half2 p = __floats2half2_rn(c[j][0], c[j][1]);
            *(unsigned*)&OUT16[(size_t)row_a * D + j * 8 + t * 2] = h2u(p);
        }
        if (row_b < N_NODES) {
            __half2 p = __floats2half2_rn(c[j][2], c[j][3]);
            *(unsigned*)&OUT16[(size_t)row_b * D + j * 8 + t * 2] = h2u(p);
        }
    }
}

// ---------------- bucket CSR fill (1 edge per thread; r11-proven) ------------
__global__ void fill_kernel(const int* __restrict__ ei) {
    int i = blockIdx.x * 256 + threadIdx.x;        // exact 640000
    int src = ei[i];
    int dst = ei[N_EDGES + i];
    int pos = atomicAdd(&g_fill[dst], 1);
    if (pos < CAP) g_sbuf[dst * CAP + pos] = (unsigned)src;
}

// Pack in place: slot -> src | (fp16(rsqrt((deg_s+1)*(deg_d+1))) << 16).
// Thread-per-4-slots; rsqrt(a)*rsqrt(b) == rsqrt(a*b) within ~1e-7.
__global__ void __launch_bounds__(256) pack_kernel() {
    int t = blockIdx.x * 256 + threadIdx.x;        // exact 800000
    int node = t >> 4;
    int base = (t & 15) * 4;
    int deg = g_fill[node];
    int degc = deg < CAP ? deg : CAP;
    if (base >= degc) return;
    float fd = (float)(deg + 1);
    uint4 v = *(const uint4*)&g_sbuf[node * CAP + base];
    int n = degc - base;
    {
        unsigned s = v.x & 0xFFFFu;
        float nm = rsqrtf(fd * (float)(g_fill[s] + 1));
        v.x = s | ((unsigned)__half_as_ushort(__float2half(nm)) << 16);
    }
    if (n > 1) {
        unsigned s = v.y & 0xFFFFu;
        float nm = rsqrtf(fd * (float)(g_fill[s] + 1));
        v.y = s | ((unsigned)__half_as_ushort(__float2half(nm)) << 16);
    }
    if (n > 2) {
        unsigned s = v.z & 0xFFFFu;
        float nm = rsqrtf(fd * (float)(g_fill[s] + 1));
        v.z = s | ((unsigned)__half_as_ushort(__float2half(nm)) << 16);
    }
    if (n > 3) {
        unsigned s = v.w & 0xFFFFu;
        float nm = rsqrtf(fd * (float)(g_fill[s] + 1));
        v.w = s | ((unsigned)__half_as_ushort(__float2half(nm)) << 16);
    }
    *(uint4*)&g_sbuf[node * CAP + base] = v;
}

// ---------------- gather core (1 warp/node, 8-edge unroll, 4 accumulators) ---
__device__ __forceinline__ void acc_edge_pk(const __half* __restrict__ H,
                                            unsigned pk, int lane,
                                            __half2& a0, __half2& a1) {
    int s = (int)(pk & 0xFFFFu);
    __half2 nm2 = u2h(__byte_perm(pk, pk, 0x3232));   // (nm, nm)
    uint2 u = ((const uint2*)(H + (size_t)s * D))[lane];
    a0 = __hfma2(u2h(u.x), nm2, a0);
    a1 = __hfma2(u2h(u.y), nm2, a1);
}

// Accumulate all edges + self-loop; result in a0 (features 2*lane..), a1 (+1).
__device__ __forceinline__ void gather_node_pk(
        const __half* __restrict__ H, int node, int lane,
        __half2& r0, __half2& r1) {
    int deg = g_fill[node];
    int degc = deg < CAP ? deg : CAP;
    float nms = __fdividef(1.f, (float)(deg + 1));    // dinv^2 (self-loop)
    __half2 a0 = __float2half2_rn(0.f), a1 = __float2half2_rn(0.f);
    __half2 b0 = __float2half2_rn(0.f), b1 = __float2half2_rn(0.f);
    {
        uint2 u = ((const uint2*)(H + (size_t)node * D))[lane];
        __half2 nm2 = __float2half2_rn(nms);
        a0 = __hfma2(u2h(u.x), nm2, a0);
        a1 = __hfma2(u2h(u.y), nm2, a1);
    }
    const uint4* sb = (const uint4*)(g_sbuf + node * CAP);
    int e = 0;
    for (; e + 8 <= degc; e += 8) {
        uint4 sa = sb[e >> 2];
        uint4 sc = sb[(e >> 2) + 1];
        acc_edge_pk(H, sa.x, lane, a0, a1);
        acc_edge_pk(H, sa.y, lane, b0, b1);
        acc_edge_pk(H, sa.z, lane, a0, a1);
        acc_edge_pk(H, sa.w, lane, b0, b1);
        acc_edge_pk(H, sc.x, lane, a0, a1);
        acc_edge_pk(H, sc.y, lane, b0, b1);
        acc_edge_pk(H, sc.z, lane, a0, a1);
        acc_edge_pk(H, sc.w, lane, b0, b1);
    }
    if (e + 4 <= degc) {
        uint4 sa = sb[e >> 2];
        acc_edge_pk(H, sa.x, lane, a0, a1);
        acc_edge_pk(H, sa.y, lane, b0, b1);
        acc_edge_pk(H, sa.z, lane, a0, a1);
        acc_edge_pk(H, sa.w, lane, b0, b1);
        e += 4;
    }
    for (; e < degc; ++e)
        acc_edge_pk(H, g_sbuf[node * CAP + e], lane, a0, a1);
    r0 = __hadd2(a0, b0);
    r1 = __hadd2(a1, b1);
}

// layer-1: z16 = fp16( relu( Ahat*h + b1 ) );  one warp per node
__global__ void __launch_bounds__(256) gather1_kernel(
        const float* __restrict__ bias) {
    int node = (blockIdx.x * blockDim.x + threadIdx.x) >> 5;   // exact 50000
    const int lane = threadIdx.x & 31;

    __half2 a0, a1;
    gather_node_pk(g_h16, node, lane, a0, a1);

    float2 f0 = __half22float2(a0);
    float2 f1 = __half22float2(a1);
    float4 b = *(const float4*)&bias[lane * 4];
    float rx = fmaxf(f0.x + b.x, 0.f);
    float ry = fmaxf(f0.y + b.y, 0.f);
    float rz = fmaxf(f1.x + b.z, 0.f);
    float rw = fmaxf(f1.y + b.w, 0.f);
    __half2 p0 = __floats2half2_rn(rx, ry);
    __half2 p1 = __floats2half2_rn(rz, rw);
    uint2 pk; pk.x = h2u(p0); pk.y = h2u(p1);
    ((uint2*)(g_z16 + (size_t)node * D))[lane] = pk;
}

// layer-2 + fused pool: g_y[batch[node]] += Ahat*z  (block = 8 nodes)
__global__ void __launch_bounds__(256) gather2_kernel(
        const int* __restrict__ batch) {
    __shared__ float part[8][128];
    __shared__ int   sgr[8];

    int node = (blockIdx.x * blockDim.x + threadIdx.x) >> 5;   // exact 50000
    const int warp = threadIdx.x >> 5;
    const int lane = threadIdx.x & 31;

    __half2 a0, a1;
    gather_node_pk(g_z16, node, lane, a0, a1);

    float2 f0 = __half22float2(a0);
    float2 f1 = __half22float2(a1);
    *(float4*)&part[warp][lane * 4] = make_float4(f0.x, f0.y, f1.x, f1.y);
    if (lane == 0) sgr[warp] = batch[node];
    __syncthreads();

    if (threadIdx.x < 128) {
        int d = threadIdx.x;
        float acc = part[0][d];
        int gc = sgr[0];
#pragma unroll
        for (int w = 1; w < 8; ++w) {
            int gw = sgr[w];
            if (gw != gc) {
                atomicAdd(&g_y[gc * D + d], acc);
                acc = 0.f; gc = gw;
            }
            acc += part[w][d];
        }
        atomicAdd(&g_y[gc * D + d], acc);
    }
}

// out[g] = (g_y[g]/cnt_g) @ W2 + b2 ; cnt via binary search on sorted batch;
// then restore zeroed-scratch invariant.
__global__ void out_clean_kernel(const int* __restrict__ batch,
                                 const float* __restrict__ W2,
                                 const float* __restrict__ b2,
                                 float* __restrict__ out) {
    int b = blockIdx.x;
    if (b < N_GRAPHS) {
        __shared__ float ys[D];
        int g = b, d = threadIdx.x;
        int lo = 0, hi = N_NODES;
        while (lo < hi) { int m = (lo + hi) >> 1; if (batch[m] < g) lo = m + 1; else hi = m; }
        int start = lo;
        lo = 0; hi = N_NODES;
        while (lo < hi) { int m = (lo + hi) >> 1; if (batch[m] < g + 1) lo = m + 1; else hi = m; }
        float cnt = fmaxf((float)(lo - start), 1.f);

        ys[d] = g_y[g * D + d] / cnt;
        g_y[g * D + d] = 0.f;            // restore invariant
        __syncthreads();
        float acc = b2[d];
#pragma unroll 8
        for (int k = 0; k < D; ++k) acc += ys[k] * W2[k * D + d];
        out[g * D + d] = acc;
    } else {
        const int nthr = (CLEAN_BLOCKS - N_GRAPHS) * 128;
        int i = (b - N_GRAPHS) * 128 + threadIdx.x;
        for (int j = i; j < N_NODES; j += nthr) g_fill[j] = 0;
    }
}

// ---------------- launch -----------------------------------------------------

extern "C" void kernel_launch(void* const* d_in, const int* in_sizes, int n_in,
                              void* d_out, int out_size) {
    const float* x     = (const float*)d_in[0];
    const int*   ei    = (const int*)d_in[1];    // int32 (JAX x64 disabled)
    const int*   batch = (const int*)d_in[2];
    const float* W1    = (const float*)d_in[3];
    const float* b1    = (const float*)d_in[4];
    const float* W2    = (const float*)d_in[5];
    const float* b2    = (const float*)d_in[6];
    float*       out   = (float*)d_out;

    __half* h16; cudaGetSymbolAddress((void**)&h16, g_h16);

    static cudaStream_t s_side = nullptr;
    static cudaEvent_t  e_fork = nullptr, e_join = nullptr;
    if (s_side == nullptr) {
        cudaStreamCreateWithFlags(&s_side, cudaStreamNonBlocking);
        cudaEventCreateWithFlags(&e_fork, cudaEventDisableTiming);
        cudaEventCreateWithFlags(&e_join, cudaEventDisableTiming);
    }

    // fork: main = GEMM1 (tensor/smem) ; side = fill -> pack (LSU)
    cudaEventRecord(e_fork, 0);
    cudaStreamWaitEvent(s_side, e_fork, 0);

    gemm_mma_kernel<<<GEMM_BLOCKS, 256>>>(x, W1, h16);

    fill_kernel<<<FILL_BLOCKS, 256, 0, s_side>>>(ei);
    pack_kernel<<<PACK_BLOCKS, 256, 0, s_side>>>();
    cudaEventRecord(e_join, s_side);
    cudaStreamWaitEvent(0, e_join, 0);

    // join: gather1 -> gather2 -> out/clean
    gather1_kernel<<<GATHER_BLOCKS, 256>>>(b1);
    gather2_kernel<<<GATHER_BLOCKS, 256>>>(batch);
    out_clean_kernel<<<CLEAN_BLOCKS, D>>>(batch, W2, b2, out);
}